// round 16
// baseline (speedup 1.0000x reference)
#include <cuda_runtime.h>
#include <cstdint>
#include <math.h>

#define IMG_V4   2097152            // 8*4*64*64*16 float4
#define TOT_V4   2621440            // + 8*1*64*64*16
#define NTHREADS 256
#define ITER     4
#define CHUNK    (NTHREADS * ITER)          // 1024 float4 = 16 KB per CTA
#define NBLOCKS  (TOT_V4 / CHUNK)           // 2560

__device__ int   g_base[8];    // packed patch-origin float4 offsets
__device__ float g_w[8];       // softmax weights

// ---------------------------------------------------------------------------
// Kernel 1: one warp, masked logit + Gumbel top-8 over 64 entries.
// ---------------------------------------------------------------------------
__global__ void topk_kernel(const float* __restrict__ logit,
                            const float* __restrict__ bg,
                            const float* __restrict__ gumbel,
                            float* __restrict__ out_ml)
{
    const int lane = threadIdx.x;  // 0..31
    float ml0 = __ldg(logit + lane)      + logf(fmaxf(1.0f - __ldg(bg + lane),      1e-8f));
    float ml1 = __ldg(logit + lane + 32) + logf(fmaxf(1.0f - __ldg(bg + lane + 32), 1e-8f));
    out_ml[lane] = ml0; out_ml[lane + 32] = ml1;

    const float o0 = ml0 + __ldg(gumbel + lane);
    const float o1 = ml1 + __ldg(gumbel + lane + 32);
    float p0 = o0, p1 = o1;
    int   j0 = 8,  j1 = 8;          // step at which my element got selected
    float m[8]; int sel[8];

    #pragma unroll
    for (int k = 0; k < 8; k++) {
        float v; int idx;
        if (p1 > p0) { v = p1; idx = lane + 32; } else { v = p0; idx = lane; }
        #pragma unroll
        for (int s = 16; s > 0; s >>= 1) {
            float ov = __shfl_xor_sync(0xffffffffu, v,   s);
            int   oi = __shfl_xor_sync(0xffffffffu, idx, s);
            if (ov > v || (ov == v && oi < idx)) { v = ov; idx = oi; }
        }
        m[k] = v; sel[k] = idx;
        if (idx == lane)      { j0 = k; p0 = -1e30f; }
        if (idx == lane + 32) { j1 = k; p1 = -1e30f; }
    }

    // all 8 softmax denominators in parallel (exp arg <= 0 always)
    float acc[8];
    #pragma unroll
    for (int k = 0; k < 8; k++) {
        float a = (k <= j0) ? expf((o0 - m[k]) * 100.0f) : 0.0f;
        if (k <= j1)  a +=    expf((o1 - m[k]) * 100.0f);
        acc[k] = a;
    }
    #pragma unroll
    for (int s = 16; s > 0; s >>= 1) {
        #pragma unroll
        for (int k = 0; k < 8; k++)
            acc[k] += __shfl_xor_sync(0xffffffffu, acc[k], s);
    }

    if (lane == 0) {
        #pragma unroll
        for (int k = 0; k < 8; k++) {
            const int n  = sel[k];
            const int hi = n >> 4, wi = (n >> 2) & 3, di = n & 3;
            g_base[k] = (hi << 20) | (wi << 12) | (di << 4);
            g_w[k]    = 1.0f / acc[k];
        }
    }
}

// ---------------------------------------------------------------------------
// Kernel 2: gather via SMEM staging + one TMA bulk store (16 KB) per CTA.
// ---------------------------------------------------------------------------
__global__ __launch_bounds__(NTHREADS)
void gather_kernel(const float4* __restrict__ img,
                   const float4* __restrict__ lab,
                   float4* __restrict__ out)
{
    __shared__ __align__(128) float4 tile[CHUNK];   // 16 KB

    cudaGridDependencySynchronize();   // HW wait for topk completion

    const int base = blockIdx.x * CHUNK + threadIdx.x;

    #pragma unroll
    for (int it = 0; it < ITER; it++) {
        const int t = base + it * NTHREADS;
        float4 v; float w;
        if (t < IMG_V4) {
            const int k = t >> 18;
            const int src = (((t >> 16) & 3) << 22) + __ldg(&g_base[k])
                          + (((t >> 10) & 63) << 14) + (((t >> 4) & 63) << 6) + (t & 15);
            v = __ldg(&img[src]);
            w = __ldg(&g_w[k]);
        } else {
            const int t2 = t - IMG_V4;
            const int k  = t2 >> 16;
            const int src = __ldg(&g_base[k])
                          + (((t2 >> 10) & 63) << 14) + (((t2 >> 4) & 63) << 6) + (t2 & 15);
            v = __ldg(&lab[src]);
            w = 1.0f;
        }
        v.x *= w; v.y *= w; v.z *= w; v.w *= w;
        tile[threadIdx.x + it * NTHREADS] = v;
    }

    // make generic-proxy STS visible to the async proxy, then bulk-store
    asm volatile("fence.proxy.async.shared::cta;" ::: "memory");
    __syncthreads();

    if (threadIdx.x == 0) {
        uint32_t saddr;
        asm("{ .reg .u64 t; cvta.to.shared.u64 t, %1; cvt.u32.u64 %0, t; }"
            : "=r"(saddr) : "l"(tile));
        const float4* gdst = out + (size_t)blockIdx.x * CHUNK;
        asm volatile(
            "cp.async.bulk.global.shared::cta.bulk_group [%0], [%1], %2;"
            :: "l"(gdst), "r"(saddr), "r"((int)(CHUNK * sizeof(float4)))
            : "memory");
        asm volatile("cp.async.bulk.commit_group;" ::: "memory");
        asm volatile("cp.async.bulk.wait_group 0;" ::: "memory");
    }
}

// ---------------------------------------------------------------------------
// Launch: topk, then gather with programmatic stream serialization (PDL).
// ---------------------------------------------------------------------------
extern "C" void kernel_launch(void* const* d_in, const int* in_sizes, int n_in,
                              void* d_out, int out_size) {
    const float* image  = (const float*)d_in[0];  // [1,4,256,256,256]
    const float* label  = (const float*)d_in[1];  // [1,1,256,256,256]
    const float* logit  = (const float*)d_in[2];  // [1,1,4,4,4]
    const float* bgmask = (const float*)d_in[3];  // [1,1,4,4,4]
    const float* gumbel = (const float*)d_in[4];  // [1,64]
    // d_in[5] = k (fixed at 8 by out_size)

    float* out    = (float*)d_out;
    float* out_ml = out + 10485760;   // img[8,4,64^3] + lab[8,1,64^3]

    topk_kernel<<<1, 32>>>(logit, bgmask, gumbel, out_ml);

    cudaLaunchConfig_t cfg = {};
    cfg.gridDim  = dim3(NBLOCKS, 1, 1);
    cfg.blockDim = dim3(NTHREADS, 1, 1);
    cfg.dynamicSmemBytes = 0;
    cfg.stream = 0;
    cudaLaunchAttribute attr[1];
    attr[0].id = cudaLaunchAttributeProgrammaticStreamSerialization;
    attr[0].val.programmaticStreamSerializationAllowed = 1;
    cfg.attrs = attr;
    cfg.numAttrs = 1;

    cudaLaunchKernelEx(&cfg, gather_kernel,
                       (const float4*)image, (const float4*)label,
                       (float4*)d_out);
}

// round 17
// speedup vs baseline: 1.2765x; 1.2765x over previous
#include <cuda_runtime.h>
#include <cstdint>
#include <math.h>

#define IMG_V4   2097152            // 8*4*64*64*16 float4
#define TOT_V4   2621440            // + 8*1*64*64*16
#define NTHREADS 256
#define NBLOCKS  (TOT_V4 / NTHREADS)    // 10240

__device__ int   g_base[8];    // packed patch-origin float4 offsets
__device__ float g_w[8];       // softmax weights

__device__ __forceinline__ unsigned f2ord(float x) {
    unsigned u = __float_as_uint(x);
    return (u & 0x80000000u) ? ~u : (u | 0x80000000u);
}
__device__ __forceinline__ float ord2f(unsigned u) {
    return __uint_as_float((u & 0x80000000u) ? (u ^ 0x80000000u) : ~u);
}

// ---------------------------------------------------------------------------
// Kernel 1: one warp, masked logit + Gumbel top-8 over 64 entries.
// redux-based argmax (short critical path) + early PDL trigger.
// ---------------------------------------------------------------------------
__global__ void topk_kernel(const float* __restrict__ logit,
                            const float* __restrict__ bg,
                            const float* __restrict__ gumbel,
                            float* __restrict__ out_ml)
{
    const int lane = threadIdx.x;  // 0..31
    float ml0 = __ldg(logit + lane)      + logf(fmaxf(1.0f - __ldg(bg + lane),      1e-8f));
    float ml1 = __ldg(logit + lane + 32) + logf(fmaxf(1.0f - __ldg(bg + lane + 32), 1e-8f));

    const float o0 = ml0 + __ldg(gumbel + lane);
    const float o1 = ml1 + __ldg(gumbel + lane + 32);
    unsigned u0 = f2ord(o0), u1 = f2ord(o1);
    int   j0 = 8,  j1 = 8;          // step at which my element got selected
    float m[8]; int sel[8];

    #pragma unroll
    for (int k = 0; k < 8; k++) {
        const unsigned mx = __reduce_max_sync(0xffffffffu, u0 > u1 ? u0 : u1);
        const unsigned b0 = __ballot_sync(0xffffffffu, u0 == mx);
        const unsigned b1 = __ballot_sync(0xffffffffu, u1 == mx);
        const int idx = b0 ? (__ffs(b0) - 1) : (31 + __ffs(b1));
        m[k] = ord2f(mx); sel[k] = idx;
        if (idx == lane)      { j0 = k; u0 = 0; }
        if (idx == lane + 32) { j1 = k; u1 = 0; }
    }

    // all 8 softmax denominators in parallel (exp arg <= 0 always)
    float acc[8];
    #pragma unroll
    for (int k = 0; k < 8; k++) {
        float a = (k <= j0) ? expf((o0 - m[k]) * 100.0f) : 0.0f;
        if (k <= j1)  a +=    expf((o1 - m[k]) * 100.0f);
        acc[k] = a;
    }
    #pragma unroll
    for (int s = 16; s > 0; s >>= 1) {
        #pragma unroll
        for (int k = 0; k < 8; k++)
            acc[k] += __shfl_xor_sync(0xffffffffu, acc[k], s);
    }

    if (lane == 0) {
        #pragma unroll
        for (int k = 0; k < 8; k++) {
            const int n  = sel[k];
            const int hi = n >> 4, wi = (n >> 2) & 3, di = n & 3;
            g_base[k] = (hi << 20) | (wi << 12) | (di << 4);
            g_w[k]    = 1.0f / acc[k];
        }
        __threadfence();
    }
    __syncwarp();
    cudaTriggerProgrammaticLaunchCompletion();   // let gather proceed now

    // non-critical output, after the trigger
    out_ml[lane] = ml0; out_ml[lane + 32] = ml1;
}

// ---------------------------------------------------------------------------
// Kernel 2: proven gather shape (1 float4/thread) + streaming stores.
// ---------------------------------------------------------------------------
__global__ __launch_bounds__(NTHREADS)
void gather_kernel(const float4* __restrict__ img,
                   const float4* __restrict__ lab,
                   float4* __restrict__ out)
{
    cudaGridDependencySynchronize();   // HW wait for topk's trigger

    const int t = blockIdx.x * NTHREADS + threadIdx.x;

    if (t < IMG_V4) {
        const int k = t >> 18;
        const int src = (((t >> 16) & 3) << 22) + __ldg(&g_base[k])
                      + (((t >> 10) & 63) << 14) + (((t >> 4) & 63) << 6) + (t & 15);
        const float w = __ldg(&g_w[k]);
        float4 v = __ldg(&img[src]);
        v.x *= w; v.y *= w; v.z *= w; v.w *= w;
        __stcs(&out[t], v);            // stream writes: protect L2 read-residency
    } else {
        const int t2 = t - IMG_V4;
        const int k  = t2 >> 16;
        const int src = __ldg(&g_base[k])
                      + (((t2 >> 10) & 63) << 14) + (((t2 >> 4) & 63) << 6) + (t2 & 15);
        __stcs(&out[t], __ldg(&lab[src]));   // weight exactly 1 (one_hot only)
    }
}

// ---------------------------------------------------------------------------
// Launch: topk, then gather with programmatic stream serialization (PDL).
// ---------------------------------------------------------------------------
extern "C" void kernel_launch(void* const* d_in, const int* in_sizes, int n_in,
                              void* d_out, int out_size) {
    const float* image  = (const float*)d_in[0];  // [1,4,256,256,256]
    const float* label  = (const float*)d_in[1];  // [1,1,256,256,256]
    const float* logit  = (const float*)d_in[2];  // [1,1,4,4,4]
    const float* bgmask = (const float*)d_in[3];  // [1,1,4,4,4]
    const float* gumbel = (const float*)d_in[4];  // [1,64]
    // d_in[5] = k (fixed at 8 by out_size)

    float* out    = (float*)d_out;
    float* out_ml = out + 10485760;   // img[8,4,64^3] + lab[8,1,64^3]

    topk_kernel<<<1, 32>>>(logit, bgmask, gumbel, out_ml);

    cudaLaunchConfig_t cfg = {};
    cfg.gridDim  = dim3(NBLOCKS, 1, 1);
    cfg.blockDim = dim3(NTHREADS, 1, 1);
    cfg.dynamicSmemBytes = 0;
    cfg.stream = 0;
    cudaLaunchAttribute attr[1];
    attr[0].id = cudaLaunchAttributeProgrammaticStreamSerialization;
    attr[0].val.programmaticStreamSerializationAllowed = 1;
    cfg.attrs = attr;
    cfg.numAttrs = 1;

    cudaLaunchKernelEx(&cfg, gather_kernel,
                       (const float4*)image, (const float4*)label,
                       (float4*)d_out);
}